// round 2
// baseline (speedup 1.0000x reference)
#include <cuda_runtime.h>
#include <cuda_bf16.h>
#include <cstdint>

#define TM        128          // rows per CTA
#define NWARPS    8
#define NTHREADS  (NWARPS * 32)
#define PXA       152          // pitch of wide activation buffers (144 max cols)
#define PXB       88           // pitch of narrow buffer (80 max cols)

// Epilogue segment descriptors: 31 segments of 8 floats after the 64 hb outputs.
// kind: 0=pos 1=action 2=active 3=street 4=num_players 5=blind 6=proj
__constant__ int c_kind[31] = {3,0,2,2,2,2,2,0,0,0,0,0,6,6,6,6,0,1,5,6,1,0,5,4,0,6,6,6,6,6,6};
__constant__ int c_col[31]  = {18,20,22,23,24,25,26,27,28,29,30,31,0,1,2,3,35,36,37,4,32,33,34,19,38,5,6,7,8,9,10};
__constant__ int c_scol[11] = {40,41,42,43,39,44,45,46,47,48,49};
__constant__ int c_widx[11] = {0,2,3,5,1,4,4,4,4,4,4};

struct Params {
    const float *state;
    const float *suit, *rank;
    const float *hW1,*hb1,*hW2,*hb2,*hW3,*hb3;
    const float *bW1,*bb1,*bW2,*bb2,*bW3,*bb3;
    const float *cW1,*cb1,*cW2,*cb2,*cW3,*cb3;
    const float *pos,*action,*active,*street,*nump,*blind;
    const float *sW,*sb;
    float *out;
    int nrows;
};

__device__ __forceinline__ float leaky(float v) { return v > 0.0f ? v : 0.01f * v; }

__device__ __forceinline__ uint32_t f2t(float x) {
    uint32_t r;
    asm("cvt.rna.tf32.f32 %0, %1;" : "=r"(r) : "f"(x));
    return r;
}
__device__ __forceinline__ float tf32f(float x) { return __uint_as_float(f2t(x)); }

__device__ __forceinline__ void mma_acc(float (&c)[4],
                                        uint32_t a0, uint32_t a1, uint32_t a2, uint32_t a3,
                                        uint32_t b0, uint32_t b1)
{
    asm volatile("mma.sync.aligned.m16n8k8.row.col.f32.tf32.tf32.f32 "
                 "{%0,%1,%2,%3}, {%4,%5,%6,%7}, {%8,%9}, {%0,%1,%2,%3};\n"
                 : "+f"(c[0]), "+f"(c[1]), "+f"(c[2]), "+f"(c[3])
                 : "r"(a0), "r"(a1), "r"(a2), "r"(a3), "r"(b0), "r"(b1));
}

// Y[warp rows][0..NOUT) = act(X @ W + b). 3xTF32. Each warp owns rows warp*16..+15.
// Weights staged per 16-k-row chunk into Whi/Wlo smem (pitch NOUT+8),
// LDG of next chunk software-pipelined behind MMA of current chunk.
template <int NIN, int NOUT, bool ACT>
__device__ __forceinline__ void dense_layer(const float* __restrict__ Wg,
                                            const float* __restrict__ bg,
                                            const float* __restrict__ Xs, int PX,
                                            float* __restrict__ Ys, int PY,
                                            float* __restrict__ Whi,
                                            float* __restrict__ Wlo,
                                            int warp, int g, int t)
{
    constexpr int NT  = NOUT / 8;       // n-tiles
    constexpr int NC  = NIN / 16;       // k-chunks
    constexpr int EPC = (16 * NOUT) / NTHREADS;  // weight elems per thread per chunk
    constexpr int PN  = NOUT + 8;

    const int tid = threadIdx.x;

    float acc[NT][4];
#pragma unroll
    for (int nt = 0; nt < NT; nt++) {
        acc[nt][0] = 0.f; acc[nt][1] = 0.f; acc[nt][2] = 0.f; acc[nt][3] = 0.f;
    }

    // prefetch chunk 0 weights
    float wreg[EPC];
#pragma unroll
    for (int i = 0; i < EPC; i++) wreg[i] = Wg[i * NTHREADS + tid];

    for (int c = 0; c < NC; c++) {
        // stage current chunk (hi/lo split) into smem
#pragma unroll
        for (int i = 0; i < EPC; i++) {
            int flat = i * NTHREADS + tid;
            int k = flat / NOUT, n = flat % NOUT;
            float w  = wreg[i];
            float hf = tf32f(w);
            Whi[k * PN + n] = hf;
            Wlo[k * PN + n] = tf32f(w - hf);
        }
        __syncthreads();

        // prefetch next chunk (overlaps with MMA below)
        if (c + 1 < NC) {
#pragma unroll
            for (int i = 0; i < EPC; i++)
                wreg[i] = Wg[(c + 1) * 16 * NOUT + i * NTHREADS + tid];
        }

#pragma unroll
        for (int kt = 0; kt < 2; kt++) {
            const int k0 = c * 16 + kt * 8;
            const float* xp = Xs + (warp * 16 + g) * PX + k0 + t;
            float x0 = xp[0];
            float x2 = xp[4];
            float x1 = xp[8 * PX];
            float x3 = xp[8 * PX + 4];
            uint32_t ah0 = f2t(x0), ah1 = f2t(x1), ah2 = f2t(x2), ah3 = f2t(x3);
            uint32_t al0 = f2t(x0 - __uint_as_float(ah0));
            uint32_t al1 = f2t(x1 - __uint_as_float(ah1));
            uint32_t al2 = f2t(x2 - __uint_as_float(ah2));
            uint32_t al3 = f2t(x3 - __uint_as_float(ah3));

            const int off = (kt * 8 + t) * PN + g;
#pragma unroll
            for (int nt = 0; nt < NT; nt++) {
                uint32_t bh0 = __float_as_uint(Whi[off + nt * 8]);
                uint32_t bh1 = __float_as_uint(Whi[off + 4 * PN + nt * 8]);
                uint32_t bl0 = __float_as_uint(Wlo[off + nt * 8]);
                uint32_t bl1 = __float_as_uint(Wlo[off + 4 * PN + nt * 8]);
                mma_acc(acc[nt], ah0, ah1, ah2, ah3, bh0, bh1);
                mma_acc(acc[nt], al0, al1, al2, al3, bh0, bh1);
                mma_acc(acc[nt], ah0, ah1, ah2, ah3, bl0, bl1);
            }
        }
        __syncthreads();
    }

    // epilogue: bias + activation, write own rows
    const int r0 = warp * 16 + g;
#pragma unroll
    for (int nt = 0; nt < NT; nt++) {
        float2 bb = __ldg((const float2*)(bg + nt * 8 + 2 * t));
        float v0 = acc[nt][0] + bb.x;
        float v1 = acc[nt][1] + bb.y;
        float v2 = acc[nt][2] + bb.x;
        float v3 = acc[nt][3] + bb.y;
        if (ACT) { v0 = leaky(v0); v1 = leaky(v1); v2 = leaky(v2); v3 = leaky(v3); }
        *(float2*)(Ys + r0 * PY + nt * 8 + 2 * t)       = make_float2(v0, v1);
        *(float2*)(Ys + (r0 + 8) * PY + nt * 8 + 2 * t) = make_float2(v2, v3);
    }
}

__global__ void __launch_bounds__(NTHREADS, 1)
preproc_kernel(Params p)
{
    extern __shared__ float smem[];
    float* XA  = smem;                    // 128 x 152
    float* XB  = XA + TM * PXA;           // 128 x 88
    float* CC  = XB + TM * PXB;           // 128 x 152
    float* WHI = CC + TM * PXA;           // 16 x 152
    float* WLO = WHI + 16 * PXA;          // 16 x 152

    const int tid  = threadIdx.x;
    const int warp = tid >> 5;
    const int lane = tid & 31;
    const int g = lane >> 2, t = lane & 3;
    const int rowBase = blockIdx.x * TM;

    // ---------- hand gather -> XB[., 0..63] (warp-private rows) ----------
    for (int r = 0; r < 16; r++) {
        int lrow = warp * 16 + r;
        int row  = rowBase + lrow;
        if (row >= p.nrows) continue;
        const float* st = p.state + (size_t)row * 50;
#pragma unroll
        for (int e = lane; e < 64; e += 32) {
            int cc = e >> 4, w = e & 15, d = e & 7;
            int col = (w < 8) ? (2 * cc + 1) : (2 * cc);
            int iv = (int)st[col];
            XB[lrow * PXB + e] = (w < 8) ? __ldg(p.suit + iv * 8 + d)
                                         : __ldg(p.rank + iv * 8 + d);
        }
    }

    // hand MLP: 64->64->64->64 (last no act) -> CC[0..63]
    dense_layer<64, 64, true >(p.hW1, p.hb1, XB, PXB, XA, PXA, WHI, WLO, warp, g, t);
    dense_layer<64, 64, true >(p.hW2, p.hb2, XA, PXA, XB, PXB, WHI, WLO, warp, g, t);
    dense_layer<64, 64, false>(p.hW3, p.hb3, XB, PXB, CC, PXA, WHI, WLO, warp, g, t);

    // ---------- board gather -> XA[., 0..79] ----------
    for (int r = 0; r < 16; r++) {
        int lrow = warp * 16 + r;
        int row  = rowBase + lrow;
        if (row >= p.nrows) continue;
        const float* st = p.state + (size_t)row * 50;
#pragma unroll
        for (int e = lane; e < 80; e += 32) {
            int cc = e >> 4, w = e & 15, d = e & 7;
            int col = (w < 8) ? (9 + 2 * cc) : (8 + 2 * cc);
            int iv = (int)st[col];
            XA[lrow * PXA + e] = (w < 8) ? __ldg(p.suit + iv * 8 + d)
                                         : __ldg(p.rank + iv * 8 + d);
        }
    }

    // board MLP: 80->80->80->80 -> CC[64..143]
    dense_layer<80, 80, true >(p.bW1, p.bb1, XA, PXA, XB, PXB, WHI, WLO, warp, g, t);
    dense_layer<80, 80, true >(p.bW2, p.bb2, XB, PXB, XA, PXA, WHI, WLO, warp, g, t);
    dense_layer<80, 80, false>(p.bW3, p.bb3, XA, PXA, CC + 64, PXA, WHI, WLO, warp, g, t);

    // hb MLP: 144->144->64->64 -> CC[0..63]
    dense_layer<144, 144, true >(p.cW1, p.cb1, CC, PXA, XA, PXA, WHI, WLO, warp, g, t);
    dense_layer<144,  64, true >(p.cW2, p.cb2, XA, PXA, XB, PXB, WHI, WLO, warp, g, t);
    dense_layer< 64,  64, false>(p.cW3, p.cb3, XB, PXB, CC, PXA, WHI, WLO, warp, g, t);

    // ---------- output epilogue (warp-private rows; no sync needed) ----------
    const float* tabs[6] = { p.pos, p.action, p.active, p.street, p.nump, p.blind };
    for (int r = 0; r < 16; r++) {
        int lrow = warp * 16 + r;
        int row  = rowBase + lrow;
        if (row >= p.nrows) continue;
        float* orow = p.out + (size_t)row * 312;
        const float* st = p.state + (size_t)row * 50;
        const float* Crow = CC + lrow * PXA;
        for (int tt = lane; tt < 312; tt += 32) {
            float v;
            if (tt < 64) {
                v = Crow[tt];
            } else {
                int s = (tt - 64) >> 3, d = (tt - 64) & 7;
                int kind = c_kind[s], col = c_col[s];
                if (kind == 6) {
                    float sc = st[c_scol[col]];
                    int w = c_widx[col];
                    v = fmaf(sc, __ldg(p.sW + w * 8 + d), __ldg(p.sb + w * 8 + d));
                } else {
                    int iv = (int)st[col];
                    v = __ldg(tabs[kind] + iv * 8 + d);
                }
            }
            orow[tt] = v;
        }
    }
}

extern "C" void kernel_launch(void* const* d_in, const int* in_sizes, int n_in,
                              void* d_out, int out_size)
{
    Params p;
    p.state  = (const float*)d_in[0];
    p.suit   = (const float*)d_in[1];
    p.rank   = (const float*)d_in[2];
    p.hW1 = (const float*)d_in[3];  p.hb1 = (const float*)d_in[4];
    p.hW2 = (const float*)d_in[5];  p.hb2 = (const float*)d_in[6];
    p.hW3 = (const float*)d_in[7];  p.hb3 = (const float*)d_in[8];
    p.bW1 = (const float*)d_in[9];  p.bb1 = (const float*)d_in[10];
    p.bW2 = (const float*)d_in[11]; p.bb2 = (const float*)d_in[12];
    p.bW3 = (const float*)d_in[13]; p.bb3 = (const float*)d_in[14];
    p.cW1 = (const float*)d_in[15]; p.cb1 = (const float*)d_in[16];
    p.cW2 = (const float*)d_in[17]; p.cb2 = (const float*)d_in[18];
    p.cW3 = (const float*)d_in[19]; p.cb3 = (const float*)d_in[20];
    p.pos    = (const float*)d_in[21];
    p.action = (const float*)d_in[22];
    p.active = (const float*)d_in[23];
    p.street = (const float*)d_in[24];
    p.nump   = (const float*)d_in[25];
    p.blind  = (const float*)d_in[26];
    p.sW     = (const float*)d_in[27];
    p.sb     = (const float*)d_in[28];
    p.out    = (float*)d_out;
    p.nrows  = out_size / 312;

    size_t smem_bytes = (size_t)(TM * PXA + TM * PXB + TM * PXA + 16 * PXA * 2) * sizeof(float);
    cudaFuncSetAttribute(preproc_kernel, cudaFuncAttributeMaxDynamicSharedMemorySize,
                         (int)smem_bytes);

    int grid = (p.nrows + TM - 1) / TM;
    preproc_kernel<<<grid, NTHREADS, smem_bytes>>>(p);
}